// round 14
// baseline (speedup 1.0000x reference)
#include <cuda_runtime.h>
#include <math.h>
#include <float.h>
#include <stdint.h>

#define NB 64
#define NK 4
#define KB 256       // NK*NB rows
#define ND 512
#define NH 512
#define G3 1536
#define NV 50257
#define NT 16

// ---------------- device state ----------------
__device__ float g_xemb[KB * ND];
__device__ float g_h[KB * NH];
__device__ float g_hnew[KB * NH];
__device__ float g_gi[KB * G3];
__device__ float g_gh[KB * G3];
__device__ float g_logits[(size_t)KB * NV];
__device__ float g_tops[KB * 4];        // top-4 QUANTIZED logp values
__device__ int   g_topx[KB * 4];
__device__ int   g_x[KB];               // [k][b]: r = k*64 + b
__device__ float g_scores[NB * NK];     // [b][k]
__device__ int   g_seqsA[NB * NK * NT];
__device__ int   g_seqsB[NB * NK * NT];
__device__ int   g_bfrom[NB * NK];

// ---------------- helpers ----------------
// Accurate exp on u in [-0.15, 0]: degree-6 Taylor, explicit fmaf (fast-math immune).
// Truncation < 2e-11 rel; result ~1 ulp accurate.
__device__ __forceinline__ float exp_narrow(float u) {
    float p = __fmaf_rn(u, 1.3888888889e-3f, 8.3333333333e-3f); // u/720 + 1/120
    p = __fmaf_rn(u, p, 4.1666666667e-2f);
    p = __fmaf_rn(u, p, 1.6666666667e-1f);
    p = __fmaf_rn(u, p, 0.5f);
    p = __fmaf_rn(u, p, 1.0f);
    p = __fmaf_rn(u, p, 1.0f);
    return p;
}

// XLA f32 tanh (rational approx; used by XLA on CPU and GPU for f32)
__device__ __forceinline__ float tanh_xla(float x) {
    float ax = fabsf(x);
    if (ax < 0.0004f) return x;
    float xc = fminf(fmaxf(x, -7.90531110763549805f), 7.90531110763549805f);
    float x2 = xc * xc;
    float p = fmaf(x2, -2.76076847742355e-16f, 2.00018790482477e-13f);
    p = fmaf(x2, p, -8.60467152213735e-11f);
    p = fmaf(x2, p, 5.12229709037114e-08f);
    p = fmaf(x2, p, 1.48572235717979e-05f);
    p = fmaf(x2, p, 6.37261928875436e-04f);
    p = fmaf(x2, p, 4.89352455891786e-03f);
    float num = xc * p;
    float q = fmaf(x2, 1.19825839466702e-06f, 1.18534705686654e-04f);
    q = fmaf(x2, q, 2.26843463243900e-03f);
    q = fmaf(x2, q, 4.89352518554385e-03f);
    return num / q;
}
__device__ __forceinline__ float sigmoid_xla(float x) {
    return 0.5f * tanh_xla(0.5f * x) + 0.5f;
}

__device__ __forceinline__ bool better(float v1, int i1, float v2, int i2) {
    // value desc, ties -> lower index (stable top_k / argsort(-x))
    return (v1 > v2) || (v1 == v2 && i1 < i2);
}

__device__ __forceinline__ void ins4(float v, int c, float tv[4], int ti[4]) {
    if (!better(v, c, tv[3], ti[3])) return;
    tv[3] = v; ti[3] = c;
#pragma unroll
    for (int j = 3; j > 0; j--) {
        if (better(tv[j], ti[j], tv[j - 1], ti[j - 1])) {
            float fv = tv[j]; tv[j] = tv[j - 1]; tv[j - 1] = fv;
            int fi = ti[j]; ti[j] = ti[j - 1]; ti[j - 1] = fi;
        }
    }
}

// ---------------- init ----------------
__global__ void init_kernel(const int* __restrict__ xs) {
    int i = blockIdx.x * blockDim.x + threadIdx.x;
    if (i < KB * NH) g_h[i] = 0.0f;
    if (i < KB) g_x[i] = xs[i & 63];
    if (i < NB * NK) g_scores[i] = 0.0f;
    if (i < NB * NK * NT) { g_seqsA[i] = 0; g_seqsB[i] = 0; }
}

// ---------------- embedding gather ----------------
__global__ void embed_kernel(const float* __restrict__ E) {
    int r = blockIdx.x;
    int tok = g_x[r];
    if (tok < 0 || tok >= NV) tok = 0;
    const float* src = E + (size_t)tok * ND;
    for (int i = threadIdx.x; i < ND; i += blockDim.x)
        g_xemb[r * ND + i] = src[i];
}

// ---------------- tiled fp32 GEMM core ----------------
template <int BM, int BN, int BK, int TM, int TN>
__device__ __forceinline__ void sgemm_core(int M, int N, int K,
                                           const float* __restrict__ A,
                                           const float* __restrict__ Bm,
                                           const float* __restrict__ bias,
                                           float* __restrict__ C) {
    constexpr int NTH = (BM / TM) * (BN / TN);
    __shared__ float As[BK][BM];
    __shared__ float Bs[BK][BN];
    const int tid = threadIdx.x;
    const int brow = blockIdx.y * BM;
    const int bcol = blockIdx.x * BN;
    const int trow = (tid / (BN / TN)) * TM;
    const int tcol = (tid % (BN / TN)) * TN;

    float acc[TM][TN];
#pragma unroll
    for (int i = 0; i < TM; i++)
#pragma unroll
        for (int j = 0; j < TN; j++) acc[i][j] = 0.0f;

    for (int k0 = 0; k0 < K; k0 += BK) {
        for (int i = tid; i < BM * BK; i += NTH) {
            int r = i / BK, c = i % BK;
            As[c][r] = A[(size_t)(brow + r) * K + k0 + c];
        }
        for (int i = tid; i < BK * BN; i += NTH) {
            int rr = i / BN, cc = i % BN;
            int col = bcol + cc;
            Bs[rr][cc] = (col < N) ? Bm[(size_t)(k0 + rr) * N + col] : 0.0f;
        }
        __syncthreads();
#pragma unroll
        for (int kk = 0; kk < BK; kk++) {
            float a[TM], b[TN];
#pragma unroll
            for (int i = 0; i < TM; i++) a[i] = As[kk][trow + i];
#pragma unroll
            for (int j = 0; j < TN; j++) b[j] = Bs[kk][tcol + j];
#pragma unroll
            for (int i = 0; i < TM; i++)
#pragma unroll
                for (int j = 0; j < TN; j++) acc[i][j] += a[i] * b[j];
        }
        __syncthreads();
    }

#pragma unroll
    for (int i = 0; i < TM; i++) {
#pragma unroll
        for (int j = 0; j < TN; j++) {
            int col = bcol + tcol + j;
            if (col < N)
                C[(size_t)(brow + trow + i) * N + col] = acc[i][j] + bias[col];
        }
    }
}

__global__ void gemm_gi(const float* __restrict__ W_ih, const float* __restrict__ b_ih) {
    sgemm_core<64, 64, 8, 4, 4>(KB, G3, ND, g_xemb, W_ih, b_ih, g_gi);
}
__global__ void gemm_gh(const float* __restrict__ W_hh, const float* __restrict__ b_hh) {
    sgemm_core<64, 64, 8, 4, 4>(KB, G3, NH, g_h, W_hh, b_hh, g_gh);
}
__global__ void gemm_logits(const float* __restrict__ W_out, const float* __restrict__ b_out) {
    sgemm_core<64, 64, 8, 4, 4>(KB, NV, NH, g_hnew, W_out, b_out, g_logits);
}

// ---------------- GRU pointwise (XLA activations) ----------------
__global__ void gru_gates() {
    int i = blockIdx.x * blockDim.x + threadIdx.x;
    if (i >= KB * NH) return;
    int r = i >> 9;
    int j = i & (NH - 1);
    const float* gi = g_gi + r * G3;
    const float* gh = g_gh + r * G3;
    float ir = gi[j], iz = gi[NH + j], ig = gi[2 * NH + j];
    float hr = gh[j], hz = gh[NH + j], hg = gh[2 * NH + j];
    float rr = sigmoid_xla(ir + hr);
    float zz = sigmoid_xla(iz + hz);
    float nn = tanh_xla(ig + rr * hg);
    float h = g_h[i];
    g_hnew[i] = (1.0f - zz) * nn + zz * h;
}

// ---------------- per-row top-4 of QUANTIZED logp ----------------
// p[c] = fl(fl(x[c]-m) - L): the fl() to ulp(10.8)=9.5e-7 collapses sub-grid
// gaps into exact ties -> stable top_k orders them by index. This tie structure
// is provably independent of L's last-ulp (uniform grid shift), so a
// double-accumulated L (~correctly rounded) is sufficient.
__global__ void topk_p_kernel() {
    const int r = blockIdx.x;
    const int tid = threadIdx.x;
    const float* row = g_logits + (size_t)r * NV;

    __shared__ float smax[256];
    __shared__ double sdbl[256];

    // phase 1: row max (order-free, exact)
    float m = -FLT_MAX;
    for (int c = tid; c < NV; c += 256) m = fmaxf(m, row[c]);
    smax[tid] = m;
    __syncthreads();
    for (int s = 128; s > 0; s >>= 1) {
        if (tid < s) smax[tid] = fmaxf(smax[tid], smax[tid + s]);
        __syncthreads();
    }
    m = smax[0];
    __syncthreads();

    // phase 2: sumexp in double (L accurate to ~1 ulp; sufficient per grid-shift proof)
    double part = 0.0;
    for (int c = tid; c < NV; c += 256)
        part += (double)exp_narrow(__fsub_rn(row[c], m));
    sdbl[tid] = part;
    __syncthreads();
    for (int s = 128; s > 0; s >>= 1) {
        if (tid < s) sdbl[tid] += sdbl[tid + s];
        __syncthreads();
    }
    const float L = (float)log(sdbl[0]);
    __syncthreads();

    // phase 3: stable top-4 over quantized p
    float tv[4] = {-FLT_MAX, -FLT_MAX, -FLT_MAX, -FLT_MAX};
    int ti[4] = {NV, NV, NV, NV};
    for (int c = tid; c < NV; c += 256) {
        float p = __fsub_rn(__fsub_rn(row[c], m), L);
        ins4(p, c, tv, ti);
    }

    __shared__ float sv[1024];
    __shared__ int si[1024];
#pragma unroll
    for (int j = 0; j < 4; j++) { sv[tid * 4 + j] = tv[j]; si[tid * 4 + j] = ti[j]; }
    __syncthreads();

    for (int s = 128; s > 0; s >>= 1) {
        if (tid < s) {
            float av[5], bv[5]; int ai[5], bi[5];
#pragma unroll
            for (int j = 0; j < 4; j++) {
                av[j] = sv[tid * 4 + j]; ai[j] = si[tid * 4 + j];
                bv[j] = sv[(tid + s) * 4 + j]; bi[j] = si[(tid + s) * 4 + j];
            }
            av[4] = -FLT_MAX; ai[4] = NV;
            bv[4] = -FLT_MAX; bi[4] = NV;
            float rv[4]; int ri[4];
            int x = 0, y = 0;
#pragma unroll
            for (int k = 0; k < 4; k++) {
                bool ta = better(av[x], ai[x], bv[y], bi[y]);
                rv[k] = ta ? av[x] : bv[y];
                ri[k] = ta ? ai[x] : bi[y];
                if (ta) x++; else y++;
            }
#pragma unroll
            for (int j = 0; j < 4; j++) { sv[tid * 4 + j] = rv[j]; si[tid * 4 + j] = ri[j]; }
        }
        __syncthreads();
    }

    if (tid == 0) {
#pragma unroll
        for (int j = 0; j < 4; j++) {
            g_tops[r * 4 + j] = sv[j];
            g_topx[r * 4 + j] = si[j];
        }
    }
}

// ---------------- beam combine / select (stable argsort(-trans) semantics) ----------------
__global__ void beam_select(int t) {
    int b = threadIdx.x;
    if (b >= NB) return;

    float cv[16];
    int cx[16];
#pragma unroll
    for (int from = 0; from < NK; from++) {
        int r = from * NB + b;
        float sc = g_scores[b * NK + from];
#pragma unroll
        for (int to = 0; to < NK; to++) {
            // tops already hold quantized logp; single fl add matches jnp
            cv[from * 4 + to] = __fadd_rn(sc, g_tops[r * 4 + to]);
            cx[from * 4 + to] = g_topx[r * 4 + to];
        }
    }

    float bs[4] = {-FLT_MAX, -FLT_MAX, -FLT_MAX, -FLT_MAX};
    int bf[4] = {16, 16, 16, 16};
#pragma unroll
    for (int f = 0; f < 16; f++) ins4(cv[f], f, bs, bf);

    const int* sin = (t & 1) ? g_seqsB : g_seqsA;
    int* sout = (t & 1) ? g_seqsA : g_seqsB;

#pragma unroll
    for (int k = 0; k < NK; k++) {
        int flat = bf[k];
        if (flat < 0 || flat > 15) flat = 0;
        int from = flat >> 2;
        int nx = cx[flat];
        g_scores[b * NK + k] = bs[k];
        g_bfrom[b * NK + k] = from;
        g_x[k * NB + b] = nx;
        for (int tt = 0; tt < NT; tt++)
            sout[b * (NK * NT) + k * NT + tt] = sin[b * (NK * NT) + from * NT + tt];
        sout[b * (NK * NT) + k * NT + t] = nx;
    }
}

// ---------------- gather hidden states from source beams ----------------
__global__ void hgather() {
    int r = blockIdx.x;
    int k = r >> 6, b = r & 63;
    int src = g_bfrom[b * NK + k] * NB + b;
    for (int i = threadIdx.x; i < NH; i += blockDim.x)
        g_h[r * NH + i] = g_hnew[src * NH + i];
}

// ---------------- final output: seqs[:, 0, :] as FLOAT32 [64,16] ----------------
__global__ void write_out(float* __restrict__ out) {
    int i = blockIdx.x * blockDim.x + threadIdx.x;
    if (i >= NB * NT) return;
    int b = i >> 4, tt = i & 15;
    out[i] = (float)g_seqsA[b * (NK * NT) + 0 * NT + tt];
}

// ---------------- host driver (graph-capturable: launches only) ----------------
extern "C" void kernel_launch(void* const* d_in, const int* in_sizes, int n_in,
                              void* d_out, int out_size) {
    const int*   xs    = (const int*)d_in[0];
    const float* E     = (const float*)d_in[1];
    const float* W_ih  = (const float*)d_in[2];
    const float* W_hh  = (const float*)d_in[3];
    const float* b_ih  = (const float*)d_in[4];
    const float* b_hh  = (const float*)d_in[5];
    const float* W_out = (const float*)d_in[6];
    const float* b_out = (const float*)d_in[7];
    float* out = (float*)d_out;

    init_kernel<<<(KB * NH + 255) / 256, 256>>>(xs);

    for (int t = 0; t < NT; t++) {
        embed_kernel<<<KB, 128>>>(E);
        gemm_gi<<<dim3(G3 / 64, KB / 64), 256>>>(W_ih, b_ih);
        gemm_gh<<<dim3(G3 / 64, KB / 64), 256>>>(W_hh, b_hh);
        gru_gates<<<(KB * NH + 255) / 256, 256>>>();
        gemm_logits<<<dim3((NV + 63) / 64, KB / 64), 256>>>(W_out, b_out);
        topk_p_kernel<<<KB, 256>>>();
        beam_select<<<1, 64>>>(t);
        hgather<<<KB, 128>>>();
    }

    write_out<<<4, 256>>>(out);
}

// round 15
// speedup vs baseline: 1.2899x; 1.2899x over previous
#include <cuda_runtime.h>
#include <math.h>
#include <float.h>
#include <stdint.h>

#define NB 64
#define NK 4
#define KB 256       // NK*NB rows
#define ND 512
#define NH 512
#define G3 1536
#define NV 50257
#define NT 16

// ---------------- device state ----------------
__device__ float g_xemb[KB * ND];
__device__ float g_h[KB * NH];
__device__ float g_hnew[KB * NH];
__device__ float g_gi[KB * G3];
__device__ float g_gh[KB * G3];
__device__ float g_logits[(size_t)KB * NV];
__device__ float g_tops[KB * 4];        // top-4 QUANTIZED logp values (leader rows only)
__device__ int   g_topx[KB * 4];
__device__ int   g_x[KB];               // [k][b]: r = k*64 + b
__device__ float g_scores[NB * NK];     // [b][k]
__device__ int   g_seqsA[NB * NK * NT];
__device__ int   g_seqsB[NB * NK * NT];
// dedup control (exact bitwise-identity tracking)
__device__ int   g_rep[NB * NK];        // rep[b][k] = lowest beam idx with identical state
__device__ int   g_leader[KB];          // per-row: rep[b][k]==k
__device__ int   g_active_k[NK];        // any leader in beam k?
__device__ int   g_hsrc[KB];            // row in g_hnew to gather h from (leader of bfrom)

// ---------------- helpers ----------------
__device__ __forceinline__ float exp_narrow(float u) {
    float p = __fmaf_rn(u, 1.3888888889e-3f, 8.3333333333e-3f);
    p = __fmaf_rn(u, p, 4.1666666667e-2f);
    p = __fmaf_rn(u, p, 1.6666666667e-1f);
    p = __fmaf_rn(u, p, 0.5f);
    p = __fmaf_rn(u, p, 1.0f);
    p = __fmaf_rn(u, p, 1.0f);
    return p;
}

__device__ __forceinline__ float tanh_xla(float x) {
    float ax = fabsf(x);
    if (ax < 0.0004f) return x;
    float xc = fminf(fmaxf(x, -7.90531110763549805f), 7.90531110763549805f);
    float x2 = xc * xc;
    float p = fmaf(x2, -2.76076847742355e-16f, 2.00018790482477e-13f);
    p = fmaf(x2, p, -8.60467152213735e-11f);
    p = fmaf(x2, p, 5.12229709037114e-08f);
    p = fmaf(x2, p, 1.48572235717979e-05f);
    p = fmaf(x2, p, 6.37261928875436e-04f);
    p = fmaf(x2, p, 4.89352455891786e-03f);
    float num = xc * p;
    float q = fmaf(x2, 1.19825839466702e-06f, 1.18534705686654e-04f);
    q = fmaf(x2, q, 2.26843463243900e-03f);
    q = fmaf(x2, q, 4.89352518554385e-03f);
    return num / q;
}
__device__ __forceinline__ float sigmoid_xla(float x) {
    return 0.5f * tanh_xla(0.5f * x) + 0.5f;
}

__device__ __forceinline__ bool better(float v1, int i1, float v2, int i2) {
    return (v1 > v2) || (v1 == v2 && i1 < i2);
}

__device__ __forceinline__ void ins4(float v, int c, float tv[4], int ti[4]) {
    if (!better(v, c, tv[3], ti[3])) return;
    tv[3] = v; ti[3] = c;
#pragma unroll
    for (int j = 3; j > 0; j--) {
        if (better(tv[j], ti[j], tv[j - 1], ti[j - 1])) {
            float fv = tv[j]; tv[j] = tv[j - 1]; tv[j - 1] = fv;
            int fi = ti[j]; ti[j] = ti[j - 1]; ti[j - 1] = fi;
        }
    }
}

// ---------------- init ----------------
__global__ void init_kernel(const int* __restrict__ xs) {
    int i = blockIdx.x * blockDim.x + threadIdx.x;
    if (i < KB * NH) g_h[i] = 0.0f;
    if (i < KB) {
        g_x[i] = xs[i & 63];
        g_leader[i] = (i < NB) ? 1 : 0;   // k==0 rows are leaders
    }
    if (i < NB * NK) { g_scores[i] = 0.0f; g_rep[i] = 0; }
    if (i < NK) g_active_k[i] = (i == 0) ? 1 : 0;
    if (i < NB * NK * NT) { g_seqsA[i] = 0; g_seqsB[i] = 0; }
}

// ---------------- embedding gather (all rows; cheap) ----------------
__global__ void embed_kernel(const float* __restrict__ E) {
    int r = blockIdx.x;
    int tok = g_x[r];
    if (tok < 0 || tok >= NV) tok = 0;
    const float* src = E + (size_t)tok * ND;
    for (int i = threadIdx.x; i < ND; i += blockDim.x)
        g_xemb[r * ND + i] = src[i];
}

// ---------------- gates GEMM (unchanged template -> bit-identical) ----------------
template <int BM, int BN, int BK, int TM, int TN>
__device__ __forceinline__ void sgemm_core(int M, int N, int K,
                                           const float* __restrict__ A,
                                           const float* __restrict__ Bm,
                                           const float* __restrict__ bias,
                                           float* __restrict__ C) {
    constexpr int NTH = (BM / TM) * (BN / TN);
    __shared__ float As[BK][BM];
    __shared__ float Bs[BK][BN];
    const int tid = threadIdx.x;
    const int brow = blockIdx.y * BM;
    const int bcol = blockIdx.x * BN;
    const int trow = (tid / (BN / TN)) * TM;
    const int tcol = (tid % (BN / TN)) * TN;

    float acc[TM][TN];
#pragma unroll
    for (int i = 0; i < TM; i++)
#pragma unroll
        for (int j = 0; j < TN; j++) acc[i][j] = 0.0f;

    for (int k0 = 0; k0 < K; k0 += BK) {
        for (int i = tid; i < BM * BK; i += NTH) {
            int r = i / BK, c = i % BK;
            As[c][r] = A[(size_t)(brow + r) * K + k0 + c];
        }
        for (int i = tid; i < BK * BN; i += NTH) {
            int rr = i / BN, cc = i % BN;
            int col = bcol + cc;
            Bs[rr][cc] = (col < N) ? Bm[(size_t)(k0 + rr) * N + col] : 0.0f;
        }
        __syncthreads();
#pragma unroll
        for (int kk = 0; kk < BK; kk++) {
            float a[TM], b[TN];
#pragma unroll
            for (int i = 0; i < TM; i++) a[i] = As[kk][trow + i];
#pragma unroll
            for (int j = 0; j < TN; j++) b[j] = Bs[kk][tcol + j];
#pragma unroll
            for (int i = 0; i < TM; i++)
#pragma unroll
                for (int j = 0; j < TN; j++) acc[i][j] += a[i] * b[j];
        }
        __syncthreads();
    }

#pragma unroll
    for (int i = 0; i < TM; i++) {
#pragma unroll
        for (int j = 0; j < TN; j++) {
            int col = bcol + tcol + j;
            if (col < N)
                C[(size_t)(brow + trow + i) * N + col] = acc[i][j] + bias[col];
        }
    }
}

// y-block == beam k (BM=64). Skip beams with no leader rows.
__global__ void gemm_gi(const float* __restrict__ W_ih, const float* __restrict__ b_ih) {
    if (g_active_k[blockIdx.y] == 0) return;
    sgemm_core<64, 64, 8, 4, 4>(KB, G3, ND, g_xemb, W_ih, b_ih, g_gi);
}
__global__ void gemm_gh(const float* __restrict__ W_hh, const float* __restrict__ b_hh) {
    if (g_active_k[blockIdx.y] == 0) return;
    sgemm_core<64, 64, 8, 4, 4>(KB, G3, NH, g_h, W_hh, b_hh, g_gh);
}

// ---------------- logits GEMM: 64x128x16 tile, float4 loads ----------------
// Bit-exact vs old tile: single accumulator per output, k ascends 0..511,
// one FFMA per step, same bias add.
#define LBM 64
#define LBN 128
#define LBK 16
__global__ void gemm_logits(const float* __restrict__ W_out, const float* __restrict__ b_out) {
    if (g_active_k[blockIdx.y] == 0) return;
    __shared__ float As[LBK][LBM];
    __shared__ float Bs[LBK][LBN];
    const int tid = threadIdx.x;               // 256 threads
    const int brow = blockIdx.y * LBM;
    const int bcol = blockIdx.x * LBN;
    const int trow = (tid >> 4) * 4;           // 16 thread-rows * TM=4
    const int tcol = (tid & 15) * 8;           // 16 thread-cols * TN=8

    float acc[4][8];
#pragma unroll
    for (int i = 0; i < 4; i++)
#pragma unroll
        for (int j = 0; j < 8; j++) acc[i][j] = 0.0f;

    const int ar = (tid * 4) >> 4;             // A row this thread loads
    const int ac = (tid * 4) & 15;             // A col (multiple of 4)
    const int brr = (tid * 8) >> 7;            // B row
    const int bcc = (tid * 8) & 127;           // B col base (multiple of 8)

    for (int k0 = 0; k0 < NH; k0 += LBK) {
        {
            const float4 av = *reinterpret_cast<const float4*>(
                &g_hnew[(size_t)(brow + ar) * NH + k0 + ac]);
            As[ac + 0][ar] = av.x; As[ac + 1][ar] = av.y;
            As[ac + 2][ar] = av.z; As[ac + 3][ar] = av.w;
        }
        {
            const float* bp = W_out + (size_t)(k0 + brr) * NV + bcol + bcc;
#pragma unroll
            for (int q = 0; q < 8; q++) {
                int col = bcol + bcc + q;
                Bs[brr][bcc + q] = (col < NV) ? bp[q] : 0.0f;
            }
        }
        __syncthreads();
#pragma unroll
        for (int kk = 0; kk < LBK; kk++) {
            float a[4], bb[8];
            *reinterpret_cast<float4*>(a) =
                *reinterpret_cast<const float4*>(&As[kk][trow]);
            *reinterpret_cast<float4*>(bb) =
                *reinterpret_cast<const float4*>(&Bs[kk][tcol]);
            *reinterpret_cast<float4*>(bb + 4) =
                *reinterpret_cast<const float4*>(&Bs[kk][tcol + 4]);
#pragma unroll
            for (int i = 0; i < 4; i++)
#pragma unroll
                for (int j = 0; j < 8; j++) acc[i][j] += a[i] * bb[j];
        }
        __syncthreads();
    }

#pragma unroll
    for (int i = 0; i < 4; i++) {
#pragma unroll
        for (int j = 0; j < 8; j++) {
            int col = bcol + tcol + j;
            if (col < NV)
                g_logits[(size_t)(brow + trow + i) * NV + col] = acc[i][j] + b_out[col];
        }
    }
}

// ---------------- GRU pointwise (all rows; garbage rows never read) ----------------
__global__ void gru_gates() {
    int i = blockIdx.x * blockDim.x + threadIdx.x;
    if (i >= KB * NH) return;
    int r = i >> 9;
    int j = i & (NH - 1);
    const float* gi = g_gi + r * G3;
    const float* gh = g_gh + r * G3;
    float ir = gi[j], iz = gi[NH + j], ig = gi[2 * NH + j];
    float hr = gh[j], hz = gh[NH + j], hg = gh[2 * NH + j];
    float rr = sigmoid_xla(ir + hr);
    float zz = sigmoid_xla(iz + hz);
    float nn = tanh_xla(ig + rr * hg);
    float h = g_h[i];
    g_hnew[i] = (1.0f - zz) * nn + zz * h;
}

// ---------------- per-row top-4 of quantized logp (leader rows only) ----------------
__global__ void topk_p_kernel() {
    const int r = blockIdx.x;
    if (g_leader[r] == 0) return;
    const int tid = threadIdx.x;
    const float* row = g_logits + (size_t)r * NV;

    __shared__ float smax[256];
    __shared__ double sdbl[256];

    float m = -FLT_MAX;
    for (int c = tid; c < NV; c += 256) m = fmaxf(m, row[c]);
    smax[tid] = m;
    __syncthreads();
    for (int s = 128; s > 0; s >>= 1) {
        if (tid < s) smax[tid] = fmaxf(smax[tid], smax[tid + s]);
        __syncthreads();
    }
    m = smax[0];
    __syncthreads();

    double part = 0.0;
    for (int c = tid; c < NV; c += 256)
        part += (double)exp_narrow(__fsub_rn(row[c], m));
    sdbl[tid] = part;
    __syncthreads();
    for (int s = 128; s > 0; s >>= 1) {
        if (tid < s) sdbl[tid] += sdbl[tid + s];
        __syncthreads();
    }
    const float L = (float)log(sdbl[0]);
    __syncthreads();

    float tv[4] = {-FLT_MAX, -FLT_MAX, -FLT_MAX, -FLT_MAX};
    int ti[4] = {NV, NV, NV, NV};
    for (int c = tid; c < NV; c += 256) {
        float p = __fsub_rn(__fsub_rn(row[c], m), L);
        ins4(p, c, tv, ti);
    }

    __shared__ float sv[1024];
    __shared__ int si[1024];
#pragma unroll
    for (int j = 0; j < 4; j++) { sv[tid * 4 + j] = tv[j]; si[tid * 4 + j] = ti[j]; }
    __syncthreads();

    for (int s = 128; s > 0; s >>= 1) {
        if (tid < s) {
            float av[5], bv[5]; int ai[5], bi[5];
#pragma unroll
            for (int j = 0; j < 4; j++) {
                av[j] = sv[tid * 4 + j]; ai[j] = si[tid * 4 + j];
                bv[j] = sv[(tid + s) * 4 + j]; bi[j] = si[(tid + s) * 4 + j];
            }
            av[4] = -FLT_MAX; ai[4] = NV;
            bv[4] = -FLT_MAX; bi[4] = NV;
            float rv[4]; int ri[4];
            int x = 0, y = 0;
#pragma unroll
            for (int k = 0; k < 4; k++) {
                bool ta = better(av[x], ai[x], bv[y], bi[y]);
                rv[k] = ta ? av[x] : bv[y];
                ri[k] = ta ? ai[x] : bi[y];
                if (ta) x++; else y++;
            }
#pragma unroll
            for (int j = 0; j < 4; j++) { sv[tid * 4 + j] = rv[j]; si[tid * 4 + j] = ri[j]; }
        }
        __syncthreads();
    }

    if (tid == 0) {
#pragma unroll
        for (int j = 0; j < 4; j++) {
            g_tops[r * 4 + j] = sv[j];
            g_topx[r * 4 + j] = si[j];
        }
    }
}

// ---------------- beam combine / select + dedup bookkeeping ----------------
__global__ void beam_select(int t) {
    __shared__ int s_active[NK];
    int b = threadIdx.x;
    if (b < NK) s_active[b] = 0;
    __syncthreads();

    if (b < NB) {
        int repp[NK];
#pragma unroll
        for (int k = 0; k < NK; k++) repp[k] = g_rep[b * NK + k];

        float cv[16];
        int cx[16];
#pragma unroll
        for (int from = 0; from < NK; from++) {
            int lr = repp[from] * NB + b;            // leader row holds the tops
            float sc = g_scores[b * NK + from];
#pragma unroll
            for (int to = 0; to < NK; to++) {
                cv[from * 4 + to] = __fadd_rn(sc, g_tops[lr * 4 + to]);
                cx[from * 4 + to] = g_topx[lr * 4 + to];
            }
        }

        float bs[4] = {-FLT_MAX, -FLT_MAX, -FLT_MAX, -FLT_MAX};
        int bf[4] = {16, 16, 16, 16};
#pragma unroll
        for (int f = 0; f < 16; f++) ins4(cv[f], f, bs, bf);

        const int* sin = (t & 1) ? g_seqsB : g_seqsA;
        int* sout = (t & 1) ? g_seqsA : g_seqsB;

        int nf[NK], nx[NK];
#pragma unroll
        for (int k = 0; k < NK; k++) {
            int flat = bf[k];
            if (flat < 0 || flat > 15) flat = 0;
            nf[k] = flat >> 2;
            nx[k] = cx[flat];
            g_scores[b * NK + k] = bs[k];
            g_x[k * NB + b] = nx[k];
            g_hsrc[k * NB + b] = repp[nf[k]] * NB + b;   // gather from source's leader
            for (int tt = 0; tt < NT; tt++)
                sout[b * (NK * NT) + k * NT + tt] = sin[b * (NK * NT) + nf[k] * NT + tt];
            sout[b * (NK * NT) + k * NT + t] = nx[k];
        }

        // new rep: identical next-state iff same source-leader AND same token (exact)
        int rnew[NK];
#pragma unroll
        for (int k = 0; k < NK; k++) {
            int rr = k;
            for (int k2 = 0; k2 < k; k2++) {
                if (repp[nf[k2]] == repp[nf[k]] && nx[k2] == nx[k]) { rr = k2; break; }
            }
            rnew[k] = rr;
            g_rep[b * NK + k] = rr;
            g_leader[k * NB + b] = (rr == k) ? 1 : 0;
            if (rr == k) s_active[k] = 1;   // benign race: all writers store 1
        }
    }
    __syncthreads();
    if (b < NK) g_active_k[b] = s_active[b];
}

// ---------------- gather hidden states via precomputed leader sources ----------------
__global__ void hgather() {
    int r = blockIdx.x;
    int src = g_hsrc[r];
    for (int i = threadIdx.x; i < NH; i += blockDim.x)
        g_h[r * NH + i] = g_hnew[src * NH + i];
}

// ---------------- final output: seqs[:, 0, :] as FLOAT32 [64,16] ----------------
__global__ void write_out(float* __restrict__ out) {
    int i = blockIdx.x * blockDim.x + threadIdx.x;
    if (i >= NB * NT) return;
    int b = i >> 4, tt = i & 15;
    out[i] = (float)g_seqsA[b * (NK * NT) + 0 * NT + tt];
}

// ---------------- host driver (graph-capturable: launches only) ----------------
extern "C" void kernel_launch(void* const* d_in, const int* in_sizes, int n_in,
                              void* d_out, int out_size) {
    const int*   xs    = (const int*)d_in[0];
    const float* E     = (const float*)d_in[1];
    const float* W_ih  = (const float*)d_in[2];
    const float* W_hh  = (const float*)d_in[3];
    const float* b_ih  = (const float*)d_in[4];
    const float* b_hh  = (const float*)d_in[5];
    const float* W_out = (const float*)d_in[6];
    const float* b_out = (const float*)d_in[7];
    float* out = (float*)d_out;

    init_kernel<<<(KB * NH + 255) / 256, 256>>>(xs);

    for (int t = 0; t < NT; t++) {
        embed_kernel<<<KB, 128>>>(E);
        gemm_gi<<<dim3(G3 / 64, NK), 256>>>(W_ih, b_ih);
        gemm_gh<<<dim3(G3 / 64, NK), 256>>>(W_hh, b_hh);
        gru_gates<<<(KB * NH + 255) / 256, 256>>>();
        gemm_logits<<<dim3((NV + LBN - 1) / LBN, NK), 256>>>(W_out, b_out);
        topk_p_kernel<<<KB, 256>>>();
        beam_select<<<1, 64>>>(t);
        hgather<<<KB, 128>>>();
    }

    write_out<<<4, 256>>>(out);
}

// round 16
// speedup vs baseline: 1.7532x; 1.3592x over previous
#include <cuda_runtime.h>
#include <math.h>
#include <float.h>
#include <stdint.h>

#define NB 64
#define NK 4
#define KB 256       // NK*NB rows
#define ND 512
#define NH 512
#define G3 1536
#define NV 50257
#define NT 16

// ---------------- device state ----------------
__device__ float g_h[KB * NH];
__device__ float g_hnew[KB * NH];
__device__ float g_gi[KB * G3];
__device__ float g_gh[KB * G3];
__device__ float g_logits[(size_t)KB * NV];
__device__ float g_tops[KB * 4];        // top-4 QUANTIZED logp values (leader rows only)
__device__ int   g_topx[KB * 4];
__device__ int   g_x[KB];               // [k][b]: r = k*64 + b
__device__ float g_scores[NB * NK];     // [b][k]
__device__ int   g_seqsA[NB * NK * NT];
__device__ int   g_seqsB[NB * NK * NT];
// dedup control (exact bitwise-identity tracking)
__device__ int   g_rep[NB * NK];        // rep[b][k] = lowest beam idx with identical state
__device__ int   g_leader[KB];          // per-row: rep[b][k]==k
__device__ int   g_active_k[NK];        // any leader in beam k?
__device__ int   g_hsrc[KB];            // row in g_hnew to gather h from (leader of bfrom)

// ---------------- helpers ----------------
__device__ __forceinline__ float exp_narrow(float u) {
    float p = __fmaf_rn(u, 1.3888888889e-3f, 8.3333333333e-3f);
    p = __fmaf_rn(u, p, 4.1666666667e-2f);
    p = __fmaf_rn(u, p, 1.6666666667e-1f);
    p = __fmaf_rn(u, p, 0.5f);
    p = __fmaf_rn(u, p, 1.0f);
    p = __fmaf_rn(u, p, 1.0f);
    return p;
}

__device__ __forceinline__ float tanh_xla(float x) {
    float ax = fabsf(x);
    if (ax < 0.0004f) return x;
    float xc = fminf(fmaxf(x, -7.90531110763549805f), 7.90531110763549805f);
    float x2 = xc * xc;
    float p = fmaf(x2, -2.76076847742355e-16f, 2.00018790482477e-13f);
    p = fmaf(x2, p, -8.60467152213735e-11f);
    p = fmaf(x2, p, 5.12229709037114e-08f);
    p = fmaf(x2, p, 1.48572235717979e-05f);
    p = fmaf(x2, p, 6.37261928875436e-04f);
    p = fmaf(x2, p, 4.89352455891786e-03f);
    float num = xc * p;
    float q = fmaf(x2, 1.19825839466702e-06f, 1.18534705686654e-04f);
    q = fmaf(x2, q, 2.26843463243900e-03f);
    q = fmaf(x2, q, 4.89352518554385e-03f);
    return num / q;
}
__device__ __forceinline__ float sigmoid_xla(float x) {
    return 0.5f * tanh_xla(0.5f * x) + 0.5f;
}

__device__ __forceinline__ bool better(float v1, int i1, float v2, int i2) {
    return (v1 > v2) || (v1 == v2 && i1 < i2);
}

__device__ __forceinline__ void ins4(float v, int c, float tv[4], int ti[4]) {
    if (!better(v, c, tv[3], ti[3])) return;
    tv[3] = v; ti[3] = c;
#pragma unroll
    for (int j = 3; j > 0; j--) {
        if (better(tv[j], ti[j], tv[j - 1], ti[j - 1])) {
            float fv = tv[j]; tv[j] = tv[j - 1]; tv[j - 1] = fv;
            int fi = ti[j]; ti[j] = ti[j - 1]; ti[j - 1] = fi;
        }
    }
}

// ---------------- init ----------------
__global__ void init_kernel(const int* __restrict__ xs) {
    int i = blockIdx.x * blockDim.x + threadIdx.x;
    if (i < KB * NH) g_h[i] = 0.0f;
    if (i < KB) {
        g_x[i] = xs[i & 63];
        g_leader[i] = (i < NB) ? 1 : 0;
    }
    if (i < NB * NK) { g_scores[i] = 0.0f; g_rep[i] = 0; }
    if (i < NK) g_active_k[i] = (i == 0) ? 1 : 0;
    if (i < NB * NK * NT) { g_seqsA[i] = 0; g_seqsB[i] = 0; }
}

// ---------------- fused gates GEMM (gi and gh in one launch) ----------------
// z=0: gi = E[g_x] @ W_ih + b_ih   (embedding gather fused into A load)
// z=1: gh = g_h    @ W_hh + b_hh
// Bit-exact vs R15: per-output single accumulator, k ascending, 1 FFMA/k,
// bias added once; only data movement differs.
#define GBK 16
__global__ void gemm_gates(const float* __restrict__ E,
                           const float* __restrict__ W_ih, const float* __restrict__ b_ih,
                           const float* __restrict__ W_hh, const float* __restrict__ b_hh) {
    const int kbeam = blockIdx.y;
    if (g_active_k[kbeam] == 0) return;
    const int which = blockIdx.z;
    __shared__ float As[GBK][64];
    __shared__ float Bs[GBK][64];
    __shared__ int stok[64];
    const int tid = threadIdx.x;              // 256 threads
    const int brow = kbeam * 64;
    const int bcol = blockIdx.x * 64;
    const float* __restrict__ W = which ? W_hh : W_ih;
    const float* __restrict__ bias = which ? b_hh : b_ih;
    float* __restrict__ C = which ? g_gh : g_gi;

    if (which == 0) {
        if (tid < 64) {
            int tok = g_x[brow + tid];
            if (tok < 0 || tok >= NV) tok = 0;
            stok[tid] = tok;
        }
    }
    __syncthreads();

    const int trow = (tid >> 4) * 4;          // 16x16 thread grid, TM=TN=4
    const int tcol = (tid & 15) * 4;
    const int ar = tid >> 2;                  // A: row 0..63
    const int ac = (tid & 3) * 4;             // A: k offset {0,4,8,12}
    const int br = tid >> 4;                  // B: k row 0..15
    const int bc = (tid & 15) * 4;            // B: col offset

    float acc[4][4];
#pragma unroll
    for (int i = 0; i < 4; i++)
#pragma unroll
        for (int j = 0; j < 4; j++) acc[i][j] = 0.0f;

    for (int k0 = 0; k0 < NH; k0 += GBK) {
        float4 av;
        if (which == 0)
            av = *reinterpret_cast<const float4*>(&E[(size_t)stok[ar] * ND + k0 + ac]);
        else
            av = *reinterpret_cast<const float4*>(&g_h[(size_t)(brow + ar) * NH + k0 + ac]);
        As[ac + 0][ar] = av.x; As[ac + 1][ar] = av.y;
        As[ac + 2][ar] = av.z; As[ac + 3][ar] = av.w;
        *reinterpret_cast<float4*>(&Bs[br][bc]) =
            *reinterpret_cast<const float4*>(&W[(size_t)(k0 + br) * G3 + bcol + bc]);
        __syncthreads();
#pragma unroll
        for (int kk = 0; kk < GBK; kk++) {
            float a[4], b[4];
            *reinterpret_cast<float4*>(a) = *reinterpret_cast<const float4*>(&As[kk][trow]);
            *reinterpret_cast<float4*>(b) = *reinterpret_cast<const float4*>(&Bs[kk][tcol]);
#pragma unroll
            for (int i = 0; i < 4; i++)
#pragma unroll
                for (int j = 0; j < 4; j++) acc[i][j] += a[i] * b[j];
        }
        __syncthreads();
    }

#pragma unroll
    for (int i = 0; i < 4; i++)
#pragma unroll
        for (int j = 0; j < 4; j++)
            C[(size_t)(brow + trow + i) * G3 + bcol + tcol + j] =
                acc[i][j] + bias[bcol + tcol + j];
}

// ---------------- logits GEMM: 64x128x16 tile (unchanged from R15) ----------------
#define LBM 64
#define LBN 128
#define LBK 16
__global__ void gemm_logits(const float* __restrict__ W_out, const float* __restrict__ b_out) {
    if (g_active_k[blockIdx.y] == 0) return;
    __shared__ float As[LBK][LBM];
    __shared__ float Bs[LBK][LBN];
    const int tid = threadIdx.x;
    const int brow = blockIdx.y * LBM;
    const int bcol = blockIdx.x * LBN;
    const int trow = (tid >> 4) * 4;
    const int tcol = (tid & 15) * 8;

    float acc[4][8];
#pragma unroll
    for (int i = 0; i < 4; i++)
#pragma unroll
        for (int j = 0; j < 8; j++) acc[i][j] = 0.0f;

    const int ar = (tid * 4) >> 4;
    const int ac = (tid * 4) & 15;
    const int brr = (tid * 8) >> 7;
    const int bcc = (tid * 8) & 127;

    for (int k0 = 0; k0 < NH; k0 += LBK) {
        {
            const float4 av = *reinterpret_cast<const float4*>(
                &g_hnew[(size_t)(brow + ar) * NH + k0 + ac]);
            As[ac + 0][ar] = av.x; As[ac + 1][ar] = av.y;
            As[ac + 2][ar] = av.z; As[ac + 3][ar] = av.w;
        }
        {
            const float* bp = W_out + (size_t)(k0 + brr) * NV + bcol + bcc;
#pragma unroll
            for (int q = 0; q < 8; q++) {
                int col = bcol + bcc + q;
                Bs[brr][bcc + q] = (col < NV) ? bp[q] : 0.0f;
            }
        }
        __syncthreads();
#pragma unroll
        for (int kk = 0; kk < LBK; kk++) {
            float a[4], bb[8];
            *reinterpret_cast<float4*>(a) =
                *reinterpret_cast<const float4*>(&As[kk][trow]);
            *reinterpret_cast<float4*>(bb) =
                *reinterpret_cast<const float4*>(&Bs[kk][tcol]);
            *reinterpret_cast<float4*>(bb + 4) =
                *reinterpret_cast<const float4*>(&Bs[kk][tcol + 4]);
#pragma unroll
            for (int i = 0; i < 4; i++)
#pragma unroll
                for (int j = 0; j < 8; j++) acc[i][j] += a[i] * bb[j];
        }
        __syncthreads();
    }

#pragma unroll
    for (int i = 0; i < 4; i++) {
#pragma unroll
        for (int j = 0; j < 8; j++) {
            int col = bcol + tcol + j;
            if (col < NV)
                g_logits[(size_t)(brow + trow + i) * NV + col] = acc[i][j] + b_out[col];
        }
    }
}

// ---------------- GRU pointwise (active beams only) ----------------
__global__ void gru_gates() {
    int i = blockIdx.x * blockDim.x + threadIdx.x;
    if (i >= KB * NH) return;
    int r = i >> 9;
    if (g_active_k[r >> 6] == 0) return;
    int j = i & (NH - 1);
    const float* gi = g_gi + r * G3;
    const float* gh = g_gh + r * G3;
    float ir = gi[j], iz = gi[NH + j], ig = gi[2 * NH + j];
    float hr = gh[j], hz = gh[NH + j], hg = gh[2 * NH + j];
    float rr = sigmoid_xla(ir + hr);
    float zz = sigmoid_xla(iz + hz);
    float nn = tanh_xla(ig + rr * hg);
    float h = g_h[i];
    g_hnew[i] = (1.0f - zz) * nn + zz * h;
}

// ---------------- per-row top-4 of quantized logp (leader rows only) ----------------
__global__ void topk_p_kernel() {
    const int r = blockIdx.x;
    if (g_leader[r] == 0) return;
    const int tid = threadIdx.x;
    const float* row = g_logits + (size_t)r * NV;

    __shared__ float smax[256];
    __shared__ double sdbl[256];

    float m = -FLT_MAX;
    for (int c = tid; c < NV; c += 256) m = fmaxf(m, row[c]);
    smax[tid] = m;
    __syncthreads();
    for (int s = 128; s > 0; s >>= 1) {
        if (tid < s) smax[tid] = fmaxf(smax[tid], smax[tid + s]);
        __syncthreads();
    }
    m = smax[0];
    __syncthreads();

    double part = 0.0;
    for (int c = tid; c < NV; c += 256)
        part += (double)exp_narrow(__fsub_rn(row[c], m));
    sdbl[tid] = part;
    __syncthreads();
    for (int s = 128; s > 0; s >>= 1) {
        if (tid < s) sdbl[tid] += sdbl[tid + s];
        __syncthreads();
    }
    const float L = (float)log(sdbl[0]);
    __syncthreads();

    float tv[4] = {-FLT_MAX, -FLT_MAX, -FLT_MAX, -FLT_MAX};
    int ti[4] = {NV, NV, NV, NV};
    for (int c = tid; c < NV; c += 256) {
        float p = __fsub_rn(__fsub_rn(row[c], m), L);
        ins4(p, c, tv, ti);
    }

    __shared__ float sv[1024];
    __shared__ int si[1024];
#pragma unroll
    for (int j = 0; j < 4; j++) { sv[tid * 4 + j] = tv[j]; si[tid * 4 + j] = ti[j]; }
    __syncthreads();

    for (int s = 128; s > 0; s >>= 1) {
        if (tid < s) {
            float av[5], bv[5]; int ai[5], bi[5];
#pragma unroll
            for (int j = 0; j < 4; j++) {
                av[j] = sv[tid * 4 + j]; ai[j] = si[tid * 4 + j];
                bv[j] = sv[(tid + s) * 4 + j]; bi[j] = si[(tid + s) * 4 + j];
            }
            av[4] = -FLT_MAX; ai[4] = NV;
            bv[4] = -FLT_MAX; bi[4] = NV;
            float rv[4]; int ri[4];
            int x = 0, y = 0;
#pragma unroll
            for (int k = 0; k < 4; k++) {
                bool ta = better(av[x], ai[x], bv[y], bi[y]);
                rv[k] = ta ? av[x] : bv[y];
                ri[k] = ta ? ai[x] : bi[y];
                if (ta) x++; else y++;
            }
#pragma unroll
            for (int j = 0; j < 4; j++) { sv[tid * 4 + j] = rv[j]; si[tid * 4 + j] = ri[j]; }
        }
        __syncthreads();
    }

    if (tid == 0) {
#pragma unroll
        for (int j = 0; j < 4; j++) {
            g_tops[r * 4 + j] = sv[j];
            g_topx[r * 4 + j] = si[j];
        }
    }
}

// ---------------- beam combine / select + dedup bookkeeping ----------------
__global__ void beam_select(int t) {
    __shared__ int s_active[NK];
    int b = threadIdx.x;
    if (b < NK) s_active[b] = 0;
    __syncthreads();

    if (b < NB) {
        int repp[NK];
#pragma unroll
        for (int k = 0; k < NK; k++) repp[k] = g_rep[b * NK + k];

        float cv[16];
        int cx[16];
#pragma unroll
        for (int from = 0; from < NK; from++) {
            int lr = repp[from] * NB + b;
            float sc = g_scores[b * NK + from];
#pragma unroll
            for (int to = 0; to < NK; to++) {
                cv[from * 4 + to] = __fadd_rn(sc, g_tops[lr * 4 + to]);
                cx[from * 4 + to] = g_topx[lr * 4 + to];
            }
        }

        float bs[4] = {-FLT_MAX, -FLT_MAX, -FLT_MAX, -FLT_MAX};
        int bf[4] = {16, 16, 16, 16};
#pragma unroll
        for (int f = 0; f < 16; f++) ins4(cv[f], f, bs, bf);

        const int* sin = (t & 1) ? g_seqsB : g_seqsA;
        int* sout = (t & 1) ? g_seqsA : g_seqsB;

        int nf[NK], nx[NK];
#pragma unroll
        for (int k = 0; k < NK; k++) {
            int flat = bf[k];
            if (flat < 0 || flat > 15) flat = 0;
            nf[k] = flat >> 2;
            nx[k] = cx[flat];
            g_scores[b * NK + k] = bs[k];
            g_x[k * NB + b] = nx[k];
            g_hsrc[k * NB + b] = repp[nf[k]] * NB + b;
            for (int tt = 0; tt < NT; tt++)
                sout[b * (NK * NT) + k * NT + tt] = sin[b * (NK * NT) + nf[k] * NT + tt];
            sout[b * (NK * NT) + k * NT + t] = nx[k];
        }

        // new rep: identical next-state iff same source-leader AND same token
#pragma unroll
        for (int k = 0; k < NK; k++) {
            int rr = k;
            for (int k2 = 0; k2 < k; k2++) {
                if (repp[nf[k2]] == repp[nf[k]] && nx[k2] == nx[k]) { rr = k2; break; }
            }
            g_rep[b * NK + k] = rr;
            g_leader[k * NB + b] = (rr == k) ? 1 : 0;
            if (rr == k) s_active[k] = 1;
        }
    }
    __syncthreads();
    if (b < NK) g_active_k[b] = s_active[b];
}

// ---------------- gather hidden states via precomputed leader sources ----------------
__global__ void hgather() {
    int r = blockIdx.x;
    int src = g_hsrc[r];
    for (int i = threadIdx.x; i < NH; i += blockDim.x)
        g_h[r * NH + i] = g_hnew[src * NH + i];
}

// ---------------- final output ----------------
__global__ void write_out(float* __restrict__ out) {
    int i = blockIdx.x * blockDim.x + threadIdx.x;
    if (i >= NB * NT) return;
    int b = i >> 4, tt = i & 15;
    out[i] = (float)g_seqsA[b * (NK * NT) + 0 * NT + tt];
}

// ---------------- host driver (graph-capturable: launches only) ----------------
extern "C" void kernel_launch(void* const* d_in, const int* in_sizes, int n_in,
                              void* d_out, int out_size) {
    const int*   xs    = (const int*)d_in[0];
    const float* E     = (const float*)d_in[1];
    const float* W_ih  = (const float*)d_in[2];
    const float* W_hh  = (const float*)d_in[3];
    const float* b_ih  = (const float*)d_in[4];
    const float* b_hh  = (const float*)d_in[5];
    const float* W_out = (const float*)d_in[6];
    const float* b_out = (const float*)d_in[7];
    float* out = (float*)d_out;

    init_kernel<<<(KB * NH + 255) / 256, 256>>>(xs);

    for (int t = 0; t < NT; t++) {
        gemm_gates<<<dim3(G3 / 64, NK, 2), 256>>>(E, W_ih, b_ih, W_hh, b_hh);
        gru_gates<<<(KB * NH + 255) / 256, 256>>>();
        gemm_logits<<<dim3((NV + LBN - 1) / LBN, NK), 256>>>(W_out, b_out);
        topk_p_kernel<<<KB, 256>>>();
        beam_select<<<1, 64>>>(t);
        hgather<<<KB, 128>>>();
    }

    write_out<<<4, 256>>>(out);
}

// round 17
// speedup vs baseline: 2.0793x; 1.1860x over previous
#include <cuda_runtime.h>
#include <math.h>
#include <float.h>
#include <stdint.h>

#define NB 64
#define NK 4
#define KB 256       // NK*NB rows
#define ND 512
#define NH 512
#define G3 1536
#define NV 50257
#define NVP 50260    // padded row stride for g_logits (16B-aligned rows)
#define NT 16

// ---------------- device state ----------------
__device__ float g_h[KB * NH];
__device__ float g_hnew[KB * NH];
__device__ float g_gi[KB * G3];
__device__ float g_gh[KB * G3];
__device__ float g_logits[(size_t)KB * NVP];
__device__ float g_tops[KB * 4];
__device__ int   g_topx[KB * 4];
__device__ int   g_x[KB];               // [k][b]: r = k*64 + b
__device__ float g_scores[NB * NK];     // [b][k]
__device__ int   g_seqsA[NB * NK * NT];
__device__ int   g_seqsB[NB * NK * NT];
// dedup control (exact bitwise-identity tracking)
__device__ int   g_rep[NB * NK];
__device__ int   g_leader[KB];
__device__ int   g_active_k[NK];
__device__ int   g_hsrc[KB];

// ---------------- helpers ----------------
__device__ __forceinline__ float exp_narrow(float u) {
    float p = __fmaf_rn(u, 1.3888888889e-3f, 8.3333333333e-3f);
    p = __fmaf_rn(u, p, 4.1666666667e-2f);
    p = __fmaf_rn(u, p, 1.6666666667e-1f);
    p = __fmaf_rn(u, p, 0.5f);
    p = __fmaf_rn(u, p, 1.0f);
    p = __fmaf_rn(u, p, 1.0f);
    return p;
}

__device__ __forceinline__ float tanh_xla(float x) {
    float ax = fabsf(x);
    if (ax < 0.0004f) return x;
    float xc = fminf(fmaxf(x, -7.90531110763549805f), 7.90531110763549805f);
    float x2 = xc * xc;
    float p = fmaf(x2, -2.76076847742355e-16f, 2.00018790482477e-13f);
    p = fmaf(x2, p, -8.60467152213735e-11f);
    p = fmaf(x2, p, 5.12229709037114e-08f);
    p = fmaf(x2, p, 1.48572235717979e-05f);
    p = fmaf(x2, p, 6.37261928875436e-04f);
    p = fmaf(x2, p, 4.89352455891786e-03f);
    float num = xc * p;
    float q = fmaf(x2, 1.19825839466702e-06f, 1.18534705686654e-04f);
    q = fmaf(x2, q, 2.26843463243900e-03f);
    q = fmaf(x2, q, 4.89352518554385e-03f);
    return num / q;
}
__device__ __forceinline__ float sigmoid_xla(float x) {
    return 0.5f * tanh_xla(0.5f * x) + 0.5f;
}

__device__ __forceinline__ bool better(float v1, int i1, float v2, int i2) {
    return (v1 > v2) || (v1 == v2 && i1 < i2);
}

__device__ __forceinline__ void ins4(float v, int c, float tv[4], int ti[4]) {
    if (!better(v, c, tv[3], ti[3])) return;
    tv[3] = v; ti[3] = c;
#pragma unroll
    for (int j = 3; j > 0; j--) {
        if (better(tv[j], ti[j], tv[j - 1], ti[j - 1])) {
            float fv = tv[j]; tv[j] = tv[j - 1]; tv[j - 1] = fv;
            int fi = ti[j]; ti[j] = ti[j - 1]; ti[j - 1] = fi;
        }
    }
}

// ---------------- init ----------------
__global__ void init_kernel(const int* __restrict__ xs) {
    int i = blockIdx.x * blockDim.x + threadIdx.x;
    if (i < KB * NH) g_h[i] = 0.0f;
    if (i < KB) {
        g_x[i] = xs[i & 63];
        g_leader[i] = (i < NB) ? 1 : 0;
    }
    if (i < NB * NK) { g_scores[i] = 0.0f; g_rep[i] = 0; }
    if (i < NK) g_active_k[i] = (i == 0) ? 1 : 0;
    if (i < NB * NK * NT) { g_seqsA[i] = 0; g_seqsB[i] = 0; }
}

// ---------------- fused gates GEMM: double-buffered, float4 loads ----------------
// z=0: gi = E[g_x] @ W_ih + b_ih ; z=1: gh = g_h @ W_hh + b_hh
// Bit-exact: single accumulator per output, k ascending, 1 FFMA/k.
#define GBK 16
__global__ void gemm_gates(const float* __restrict__ E,
                           const float* __restrict__ W_ih, const float* __restrict__ b_ih,
                           const float* __restrict__ W_hh, const float* __restrict__ b_hh) {
    const int kbeam = blockIdx.y;
    if (g_active_k[kbeam] == 0) return;
    const int which = blockIdx.z;
    __shared__ float As[2][GBK][64];
    __shared__ float Bs[2][GBK][64];
    __shared__ int stok[64];
    const int tid = threadIdx.x;              // 256
    const int brow = kbeam * 64;
    const int bcol = blockIdx.x * 64;
    const float* __restrict__ W = which ? W_hh : W_ih;
    const float* __restrict__ bias = which ? b_hh : b_ih;
    float* __restrict__ C = which ? g_gh : g_gi;

    if (which == 0 && tid < 64) {
        int tok = g_x[brow + tid];
        if (tok < 0 || tok >= NV) tok = 0;
        stok[tid] = tok;
    }
    __syncthreads();

    const int trow = (tid >> 4) * 4;
    const int tcol = (tid & 15) * 4;
    const int ar = tid >> 2;                  // 0..63
    const int ac = (tid & 3) * 4;             // 0,4,8,12
    const int br = tid >> 4;                  // 0..15
    const int bc = (tid & 15) * 4;

    float acc[4][4];
#pragma unroll
    for (int i = 0; i < 4; i++)
#pragma unroll
        for (int j = 0; j < 4; j++) acc[i][j] = 0.0f;

    // preload tile 0
    {
        float4 av = (which == 0)
            ? *reinterpret_cast<const float4*>(&E[(size_t)stok[ar] * ND + ac])
            : *reinterpret_cast<const float4*>(&g_h[(size_t)(brow + ar) * NH + ac]);
        As[0][ac + 0][ar] = av.x; As[0][ac + 1][ar] = av.y;
        As[0][ac + 2][ar] = av.z; As[0][ac + 3][ar] = av.w;
        *reinterpret_cast<float4*>(&Bs[0][br][bc]) =
            *reinterpret_cast<const float4*>(&W[(size_t)br * G3 + bcol + bc]);
    }
    __syncthreads();

#pragma unroll 1
    for (int k0 = 0; k0 < NH; k0 += GBK) {
        const int cur = (k0 / GBK) & 1, nxt = cur ^ 1;
        if (k0 + GBK < NH) {
            float4 av = (which == 0)
                ? *reinterpret_cast<const float4*>(&E[(size_t)stok[ar] * ND + k0 + GBK + ac])
                : *reinterpret_cast<const float4*>(&g_h[(size_t)(brow + ar) * NH + k0 + GBK + ac]);
            As[nxt][ac + 0][ar] = av.x; As[nxt][ac + 1][ar] = av.y;
            As[nxt][ac + 2][ar] = av.z; As[nxt][ac + 3][ar] = av.w;
            *reinterpret_cast<float4*>(&Bs[nxt][br][bc]) =
                *reinterpret_cast<const float4*>(&W[(size_t)(k0 + GBK + br) * G3 + bcol + bc]);
        }
#pragma unroll
        for (int kk = 0; kk < GBK; kk++) {
            float a[4], b[4];
            *reinterpret_cast<float4*>(a) = *reinterpret_cast<const float4*>(&As[cur][kk][trow]);
            *reinterpret_cast<float4*>(b) = *reinterpret_cast<const float4*>(&Bs[cur][kk][tcol]);
#pragma unroll
            for (int i = 0; i < 4; i++)
#pragma unroll
                for (int j = 0; j < 4; j++) acc[i][j] += a[i] * b[j];
        }
        __syncthreads();
    }

#pragma unroll
    for (int i = 0; i < 4; i++)
#pragma unroll
        for (int j = 0; j < 4; j++)
            C[(size_t)(brow + trow + i) * G3 + bcol + tcol + j] =
                acc[i][j] + bias[bcol + tcol + j];
}

// ---------------- logits GEMM: 64x64x16, double-buffered ----------------
#define LBM 64
#define LBN 64
#define LBK 16
#define LNBLK ((NV + LBN - 1) / LBN)   // 786
__global__ void gemm_logits(const float* __restrict__ W_out, const float* __restrict__ b_out) {
    if (g_active_k[blockIdx.y] == 0) return;
    __shared__ float As[2][LBK][LBM];
    __shared__ float Bs[2][LBK][LBN];
    const int tid = threadIdx.x;               // 256
    const int brow = blockIdx.y * LBM;
    const int bcol = blockIdx.x * LBN;
    const int trow = (tid >> 4) * 4;
    const int tcol = (tid & 15) * 4;
    const int ar = tid >> 2;                   // 0..63
    const int ac = (tid & 3) * 4;

    float acc[4][4];
#pragma unroll
    for (int i = 0; i < 4; i++)
#pragma unroll
        for (int j = 0; j < 4; j++) acc[i][j] = 0.0f;

    // loaders: A vectorized (NH stride 16B-aligned); B scalar (NV odd -> unaligned rows)
    auto loadA = [&](int buf, int k0) {
        const float4 av = *reinterpret_cast<const float4*>(
            &g_hnew[(size_t)(brow + ar) * NH + k0 + ac]);
        As[buf][ac + 0][ar] = av.x; As[buf][ac + 1][ar] = av.y;
        As[buf][ac + 2][ar] = av.z; As[buf][ac + 3][ar] = av.w;
    };
    auto loadB = [&](int buf, int k0) {
#pragma unroll
        for (int i = tid; i < LBK * LBN; i += 256) {
            int r = i >> 6, c = i & 63;
            int col = bcol + c;
            Bs[buf][r][c] = (col < NV) ? W_out[(size_t)(k0 + r) * NV + col] : 0.0f;
        }
    };

    loadA(0, 0); loadB(0, 0);
    __syncthreads();

#pragma unroll 1
    for (int k0 = 0; k0 < NH; k0 += LBK) {
        const int cur = (k0 / LBK) & 1, nxt = cur ^ 1;
        if (k0 + LBK < NH) { loadA(nxt, k0 + LBK); loadB(nxt, k0 + LBK); }
#pragma unroll
        for (int kk = 0; kk < LBK; kk++) {
            float a[4], b[4];
            *reinterpret_cast<float4*>(a) = *reinterpret_cast<const float4*>(&As[cur][kk][trow]);
            *reinterpret_cast<float4*>(b) = *reinterpret_cast<const float4*>(&Bs[cur][kk][tcol]);
#pragma unroll
            for (int i = 0; i < 4; i++)
#pragma unroll
                for (int j = 0; j < 4; j++) acc[i][j] += a[i] * b[j];
        }
        __syncthreads();
    }

#pragma unroll
    for (int i = 0; i < 4; i++) {
#pragma unroll
        for (int j = 0; j < 4; j++) {
            int col = bcol + tcol + j;
            if (col < NV)
                g_logits[(size_t)(brow + trow + i) * NVP + col] = acc[i][j] + b_out[col];
        }
    }
}

// ---------------- GRU pointwise (active beams only) ----------------
__global__ void gru_gates() {
    int i = blockIdx.x * blockDim.x + threadIdx.x;
    if (i >= KB * NH) return;
    int r = i >> 9;
    if (g_active_k[r >> 6] == 0) return;
    int j = i & (NH - 1);
    const float* gi = g_gi + r * G3;
    const float* gh = g_gh + r * G3;
    float ir = gi[j], iz = gi[NH + j], ig = gi[2 * NH + j];
    float hr = gh[j], hz = gh[NH + j], hg = gh[2 * NH + j];
    float rr = sigmoid_xla(ir + hr);
    float zz = sigmoid_xla(iz + hz);
    float nn = tanh_xla(ig + rr * hg);
    float h = g_h[i];
    g_hnew[i] = (1.0f - zz) * nn + zz * h;
}

// ---------------- per-row top-4 of quantized logp: 1024 thr, float4 ----------------
#define TKT 1024
__global__ void topk_p_kernel() {
    const int r = blockIdx.x;
    if (g_leader[r] == 0) return;
    const int tid = threadIdx.x;
    const float* row = g_logits + (size_t)r * NVP;
    const float4* row4 = reinterpret_cast<const float4*>(row);
    const int N4 = NV / 4;                    // 12564 full float4s; tail at 50256

    __shared__ float smax[TKT];
    __shared__ double sdbl[TKT];

    // pass 1: max
    float m = -FLT_MAX;
    for (int i = tid; i < N4; i += TKT) {
        float4 v = row4[i];
        m = fmaxf(m, fmaxf(fmaxf(v.x, v.y), fmaxf(v.z, v.w)));
    }
    if (tid == 0) m = fmaxf(m, row[N4 * 4]);  // tail element 50256
    smax[tid] = m;
    __syncthreads();
    for (int s = TKT / 2; s > 0; s >>= 1) {
        if (tid < s) smax[tid] = fmaxf(smax[tid], smax[tid + s]);
        __syncthreads();
    }
    m = smax[0];
    __syncthreads();

    // pass 2: sumexp in double (order-free; grid-shift proof makes ~1ulp L sufficient)
    double part = 0.0;
    for (int i = tid; i < N4; i += TKT) {
        float4 v = row4[i];
        part += (double)exp_narrow(__fsub_rn(v.x, m));
        part += (double)exp_narrow(__fsub_rn(v.y, m));
        part += (double)exp_narrow(__fsub_rn(v.z, m));
        part += (double)exp_narrow(__fsub_rn(v.w, m));
    }
    if (tid == 0) part += (double)exp_narrow(__fsub_rn(row[N4 * 4], m));
    sdbl[tid] = part;
    __syncthreads();
    for (int s = TKT / 2; s > 0; s >>= 1) {
        if (tid < s) sdbl[tid] += sdbl[tid + s];
        __syncthreads();
    }
    const float L = (float)log(sdbl[0]);
    __syncthreads();

    // pass 3: stable top-4 over quantized p
    float tv[4] = {-FLT_MAX, -FLT_MAX, -FLT_MAX, -FLT_MAX};
    int ti[4] = {NV, NV, NV, NV};
    for (int i = tid; i < N4; i += TKT) {
        float4 v = row4[i];
        int c = i * 4;
        ins4(__fsub_rn(__fsub_rn(v.x, m), L), c + 0, tv, ti);
        ins4(__fsub_rn(__fsub_rn(v.y, m), L), c + 1, tv, ti);
        ins4(__fsub_rn(__fsub_rn(v.z, m), L), c + 2, tv, ti);
        ins4(__fsub_rn(__fsub_rn(v.w, m), L), c + 3, tv, ti);
    }
    if (tid == 0)
        ins4(__fsub_rn(__fsub_rn(row[N4 * 4], m), L), N4 * 4, tv, ti);

    __shared__ float sv[TKT * 4];
    __shared__ int si[TKT * 4];
#pragma unroll
    for (int j = 0; j < 4; j++) { sv[tid * 4 + j] = tv[j]; si[tid * 4 + j] = ti[j]; }
    __syncthreads();

    for (int s = TKT / 2; s > 0; s >>= 1) {
        if (tid < s) {
            float av[5], bv[5]; int ai[5], bi[5];
#pragma unroll
            for (int j = 0; j < 4; j++) {
                av[j] = sv[tid * 4 + j]; ai[j] = si[tid * 4 + j];
                bv[j] = sv[(tid + s) * 4 + j]; bi[j] = si[(tid + s) * 4 + j];
            }
            av[4] = -FLT_MAX; ai[4] = NV;
            bv[4] = -FLT_MAX; bi[4] = NV;
            float rv[4]; int ri[4];
            int x = 0, y = 0;
#pragma unroll
            for (int k = 0; k < 4; k++) {
                bool ta = better(av[x], ai[x], bv[y], bi[y]);
                rv[k] = ta ? av[x] : bv[y];
                ri[k] = ta ? ai[x] : bi[y];
                if (ta) x++; else y++;
            }
#pragma unroll
            for (int j = 0; j < 4; j++) { sv[tid * 4 + j] = rv[j]; si[tid * 4 + j] = ri[j]; }
        }
        __syncthreads();
    }

    if (tid == 0) {
#pragma unroll
        for (int j = 0; j < 4; j++) {
            g_tops[r * 4 + j] = sv[j];
            g_topx[r * 4 + j] = si[j];
        }
    }
}

// ---------------- beam combine / select + dedup bookkeeping ----------------
__global__ void beam_select(int t) {
    __shared__ int s_active[NK];
    int b = threadIdx.x;
    if (b < NK) s_active[b] = 0;
    __syncthreads();

    if (b < NB) {
        int repp[NK];
#pragma unroll
        for (int k = 0; k < NK; k++) repp[k] = g_rep[b * NK + k];

        float cv[16];
        int cx[16];
#pragma unroll
        for (int from = 0; from < NK; from++) {
            int lr = repp[from] * NB + b;
            float sc = g_scores[b * NK + from];
#pragma unroll
            for (int to = 0; to < NK; to++) {
                cv[from * 4 + to] = __fadd_rn(sc, g_tops[lr * 4 + to]);
                cx[from * 4 + to] = g_topx[lr * 4 + to];
            }
        }

        float bs[4] = {-FLT_MAX, -FLT_MAX, -FLT_MAX, -FLT_MAX};
        int bf[4] = {16, 16, 16, 16};
#pragma unroll
        for (int f = 0; f < 16; f++) ins4(cv[f], f, bs, bf);

        const int* sin = (t & 1) ? g_seqsB : g_seqsA;
        int* sout = (t & 1) ? g_seqsA : g_seqsB;

        int nf[NK], nx[NK];
#pragma unroll
        for (int k = 0; k < NK; k++) {
            int flat = bf[k];
            if (flat < 0 || flat > 15) flat = 0;
            nf[k] = flat >> 2;
            nx[k] = cx[flat];
            g_scores[b * NK + k] = bs[k];
            g_x[k * NB + b] = nx[k];
            g_hsrc[k * NB + b] = repp[nf[k]] * NB + b;
            for (int tt = 0; tt < NT; tt++)
                sout[b * (NK * NT) + k * NT + tt] = sin[b * (NK * NT) + nf[k] * NT + tt];
            sout[b * (NK * NT) + k * NT + t] = nx[k];
        }

#pragma unroll
        for (int k = 0; k < NK; k++) {
            int rr = k;
            for (int k2 = 0; k2 < k; k2++) {
                if (repp[nf[k2]] == repp[nf[k]] && nx[k2] == nx[k]) { rr = k2; break; }
            }
            g_rep[b * NK + k] = rr;
            g_leader[k * NB + b] = (rr == k) ? 1 : 0;
            if (rr == k) s_active[k] = 1;
        }
    }
    __syncthreads();
    if (b < NK) g_active_k[b] = s_active[b];
}

// ---------------- gather hidden states via precomputed leader sources ----------------
__global__ void hgather() {
    int r = blockIdx.x;
    int src = g_hsrc[r];
    for (int i = threadIdx.x; i < NH; i += blockDim.x)
        g_h[r * NH + i] = g_hnew[src * NH + i];
}

// ---------------- final output ----------------
__global__ void write_out(float* __restrict__ out) {
    int i = blockIdx.x * blockDim.x + threadIdx.x;
    if (i >= NB * NT) return;
    int b = i >> 4, tt = i & 15;
    out[i] = (float)g_seqsA[b * (NK * NT) + 0 * NT + tt];
}

// ---------------- host driver (graph-capturable: launches only) ----------------
extern "C" void kernel_launch(void* const* d_in, const int* in_sizes, int n_in,
                              void* d_out, int out_size) {
    const int*   xs    = (const int*)d_in[0];
    const float* E     = (const float*)d_in[1];
    const float* W_ih  = (const float*)d_in[2];
    const float* W_hh  = (const float*)d_in[3];
    const float* b_ih  = (const float*)d_in[4];
    const float* b_hh  = (const float*)d_in[5];
    const float* W_out = (const float*)d_in[6];
    const float* b_out = (const float*)d_in[7];
    float* out = (float*)d_out;

    init_kernel<<<(KB * NH + 255) / 256, 256>>>(xs);

    for (int t = 0; t < NT; t++) {
        gemm_gates<<<dim3(G3 / 64, NK, 2), 256>>>(E, W_ih, b_ih, W_hh, b_hh);
        gru_gates<<<(KB * NH + 255) / 256, 256>>>();
        gemm_logits<<<dim3(LNBLK, NK), 256>>>(W_out, b_out);
        topk_p_kernel<<<KB, TKT>>>();
        beam_select<<<1, 64>>>(t);
        hgather<<<KB, 128>>>();
    }

    write_out<<<4, 256>>>(out);
}